// round 1
// baseline (speedup 1.0000x reference)
#include <cuda_runtime.h>
#include <cuda_bf16.h>
#include <cstdint>

#define NN      50000
#define NE      400000
#define NG      128
#define IN_DIM  768
#define HID     128
#define NCLS    11
#define BN_EPS  1e-5f

// ---------------- scratch (device globals; no allocation allowed) ----------------
__device__ float    g_y[(size_t)NN * 256];      // [NN,256]: cols 0..127 = h@Wl.T, 128..255 = h@Wr.T
__device__ float    g_hpre[(size_t)NN * HID];   // pre-BN activations
__device__ float    g_h[(size_t)NN * HID];      // post-BN(+relu) activations
__device__ int      g_deg[NN];
__device__ int      g_off[NN + 1];
__device__ int      g_cursor[NN];
__device__ int      g_csr[NE];                  // src ids bucketed by dst
__device__ float    g_stats[256];               // [0:128)=sum, [128:256)=sumsq
__device__ unsigned g_pool[NG * HID];           // order-preserving-encoded max

// ---------------- helpers ----------------
__device__ __forceinline__ unsigned fenc(float f) {
    unsigned u = __float_as_uint(f);
    return (u >> 31) ? ~u : (u | 0x80000000u);
}
__device__ __forceinline__ float fdec(unsigned e) {
    return (e >> 31) ? __uint_as_float(e & 0x7fffffffu) : __uint_as_float(~e);
}

// ---------------- CSR build ----------------
__global__ void zero_deg_k() {
    int i = blockIdx.x * blockDim.x + threadIdx.x;
    if (i < NN) g_deg[i] = 0;
}

__global__ void hist_k(const int* __restrict__ dst) {
    int e = blockIdx.x * blockDim.x + threadIdx.x;
    if (e < NE) atomicAdd(&g_deg[dst[e]], 1);
}

__global__ void scan_k() {
    __shared__ int sm[1024];
    __shared__ int carry;
    int t = threadIdx.x;
    if (t == 0) carry = 0;
    __syncthreads();
    for (int base = 0; base < NN; base += 1024) {
        int i = base + t;
        int v = (i < NN) ? g_deg[i] : 0;
        sm[t] = v;
        __syncthreads();
        #pragma unroll
        for (int s = 1; s < 1024; s <<= 1) {
            int add = (t >= s) ? sm[t - s] : 0;
            __syncthreads();
            sm[t] += add;
            __syncthreads();
        }
        int excl = carry + sm[t] - v;
        if (i < NN) { g_off[i] = excl; g_cursor[i] = excl; }
        __syncthreads();
        if (t == 0) carry += sm[1023];
        __syncthreads();
    }
    if (t == 0) g_off[NN] = carry;
}

__global__ void fill_k(const int* __restrict__ src, const int* __restrict__ dst) {
    int e = blockIdx.x * blockDim.x + threadIdx.x;
    if (e < NE) {
        int p = atomicAdd(&g_cursor[dst[e]], 1);
        g_csr[p] = src[e];
    }
}

// ---------------- GEMM: g_y[:, col0:col0+128] = A[M,K] @ W[128,K].T ----------------
// BM=128, BN=128(=full N), BK=8, 256 threads, 8x8 per thread.
__global__ __launch_bounds__(256, 2)
void sgemm128(const float* __restrict__ Aext, int useH,
              const float* __restrict__ W, int M, int K, int col0) {
    const float* __restrict__ A = useH ? (const float*)g_h : Aext;
    __shared__ float As[8][128];
    __shared__ float Bs[8][128];

    const int tid = threadIdx.x;          // 0..255
    const int tx  = tid & 15;             // N direction
    const int ty  = tid >> 4;             // M direction
    const int row0 = blockIdx.x * 128;

    const int la_row = tid >> 1;          // 0..127
    const int la_k4  = (tid & 1) * 4;     // 0 or 4

    float acc[8][8];
    #pragma unroll
    for (int i = 0; i < 8; i++)
        #pragma unroll
        for (int j = 0; j < 8; j++) acc[i][j] = 0.f;

    for (int k0 = 0; k0 < K; k0 += 8) {
        int ar = row0 + la_row;
        float4 av = make_float4(0.f, 0.f, 0.f, 0.f);
        if (ar < M)
            av = *reinterpret_cast<const float4*>(A + (size_t)ar * K + k0 + la_k4);
        As[la_k4 + 0][la_row] = av.x;
        As[la_k4 + 1][la_row] = av.y;
        As[la_k4 + 2][la_row] = av.z;
        As[la_k4 + 3][la_row] = av.w;

        float4 bv = *reinterpret_cast<const float4*>(W + (size_t)la_row * K + k0 + la_k4);
        Bs[la_k4 + 0][la_row] = bv.x;
        Bs[la_k4 + 1][la_row] = bv.y;
        Bs[la_k4 + 2][la_row] = bv.z;
        Bs[la_k4 + 3][la_row] = bv.w;
        __syncthreads();

        #pragma unroll
        for (int k = 0; k < 8; k++) {
            float ra[8], rb[8];
            #pragma unroll
            for (int i = 0; i < 8; i++) ra[i] = As[k][ty * 8 + i];
            #pragma unroll
            for (int j = 0; j < 8; j++) rb[j] = Bs[k][tx * 8 + j];
            #pragma unroll
            for (int i = 0; i < 8; i++)
                #pragma unroll
                for (int j = 0; j < 8; j++)
                    acc[i][j] += ra[i] * rb[j];
        }
        __syncthreads();
    }

    #pragma unroll
    for (int i = 0; i < 8; i++) {
        int r = row0 + ty * 8 + i;
        if (r < M) {
            float* yr = g_y + (size_t)r * 256 + col0 + tx * 8;
            float4 o0 = make_float4(acc[i][0], acc[i][1], acc[i][2], acc[i][3]);
            float4 o1 = make_float4(acc[i][4], acc[i][5], acc[i][6], acc[i][7]);
            *reinterpret_cast<float4*>(yr)     = o0;
            *reinterpret_cast<float4*>(yr + 4) = o1;
        }
    }
}

// ---------------- gather (CSR) + combine: hpre = mean_agg(yl) + yr + b ----------------
__global__ void gather_combine(const float* __restrict__ bias) {
    int warp = (blockIdx.x * blockDim.x + threadIdx.x) >> 5;
    int lane = threadIdx.x & 31;
    if (warp >= NN) return;
    int e0 = g_off[warp], e1 = g_off[warp + 1];
    float4 acc = make_float4(0.f, 0.f, 0.f, 0.f);
    for (int e = e0; e < e1; e++) {
        int s = g_csr[e];
        float4 v = reinterpret_cast<const float4*>(g_y + (size_t)s * 256)[lane];
        acc.x += v.x; acc.y += v.y; acc.z += v.z; acc.w += v.w;
    }
    float invd = 1.f / fmaxf((float)(e1 - e0), 1.f);
    float4 r  = reinterpret_cast<const float4*>(g_y + (size_t)warp * 256 + 128)[lane];
    float4 b4 = reinterpret_cast<const float4*>(bias)[lane];
    float4 o;
    o.x = acc.x * invd + r.x + b4.x;
    o.y = acc.y * invd + r.y + b4.y;
    o.z = acc.z * invd + r.z + b4.z;
    o.w = acc.w * invd + r.w + b4.w;
    reinterpret_cast<float4*>(g_hpre + (size_t)warp * HID)[lane] = o;
}

// ---------------- BatchNorm ----------------
__global__ void zero_stats_k() { g_stats[threadIdx.x] = 0.f; }

__global__ void bn_stats_k() {
    int f = threadIdx.x;  // 128
    float s = 0.f, s2 = 0.f;
    for (int r = blockIdx.x; r < NN; r += gridDim.x) {
        float v = g_hpre[(size_t)r * HID + f];
        s += v; s2 += v * v;
    }
    atomicAdd(&g_stats[f], s);
    atomicAdd(&g_stats[f + 128], s2);
}

__global__ void bn_norm_k(const float* __restrict__ gamma, const float* __restrict__ beta,
                          int do_relu) {
    int f = threadIdx.x;
    float mean = g_stats[f] * (1.f / NN);
    float var  = g_stats[f + 128] * (1.f / NN) - mean * mean;
    float rstd = rsqrtf(var + BN_EPS);
    float g = gamma[f] * rstd;
    float b = beta[f] - mean * g;
    for (int r = blockIdx.x; r < NN; r += gridDim.x) {
        float v = g_hpre[(size_t)r * HID + f] * g + b;
        if (do_relu) v = fmaxf(v, 0.f);
        g_h[(size_t)r * HID + f] = v;
    }
}

// ---------------- global max pool (batch is sorted) ----------------
__global__ void pool_init_k() {
    g_pool[blockIdx.x * HID + threadIdx.x] = 0x007fffffu;  // fenc(-inf)
}

#define POOL_CHUNK 512
__global__ void pool_max_k(const int* __restrict__ batch) {
    int f = threadIdx.x;  // 128
    int r0 = blockIdx.x * POOL_CHUNK;
    int r1 = min(r0 + POOL_CHUNK, NN);
    int cur = -1;
    float m = -3.4e38f;
    for (int r = r0; r < r1; r++) {
        int gi = batch[r];
        if (gi != cur) {
            if (cur >= 0) atomicMax(&g_pool[cur * HID + f], fenc(m));
            cur = gi;
            m = -3.4e38f;
        }
        m = fmaxf(m, g_h[(size_t)r * HID + f]);
    }
    if (cur >= 0) atomicMax(&g_pool[cur * HID + f], fenc(m));
}

// ---------------- final linear: out[g] = pooled[g] @ Wlin.T + blin ----------------
__global__ void final_linear_k(const float* __restrict__ Wlin, const float* __restrict__ blin,
                               float* __restrict__ out) {
    __shared__ float sh[HID];
    int g = blockIdx.x, t = threadIdx.x;
    sh[t] = fdec(g_pool[g * HID + t]);
    __syncthreads();
    if (t < NCLS) {
        float a = blin[t];
        #pragma unroll 8
        for (int k = 0; k < HID; k++) a += sh[k] * Wlin[t * HID + k];
        out[g * NCLS + t] = a;
    }
}

// ---------------- launch ----------------
extern "C" void kernel_launch(void* const* d_in, const int* in_sizes, int n_in,
                              void* d_out, int out_size) {
    const float* x    = (const float*)d_in[0];
    const int*   src  = (const int*)d_in[1];
    const int*   dst  = src + NE;
    const int*   batch = (const int*)d_in[2];
    const float* W1l = (const float*)d_in[3];
    const float* b1  = (const float*)d_in[4];
    const float* W1r = (const float*)d_in[5];
    const float* g1  = (const float*)d_in[6];
    const float* be1 = (const float*)d_in[7];
    const float* W2l = (const float*)d_in[8];
    const float* b2  = (const float*)d_in[9];
    const float* W2r = (const float*)d_in[10];
    const float* g2  = (const float*)d_in[11];
    const float* be2 = (const float*)d_in[12];
    const float* W3l = (const float*)d_in[13];
    const float* b3  = (const float*)d_in[14];
    const float* W3r = (const float*)d_in[15];
    const float* g3  = (const float*)d_in[16];
    const float* be3 = (const float*)d_in[17];
    const float* Wlin = (const float*)d_in[18];
    const float* blin = (const float*)d_in[19];
    float* out = (float*)d_out;

    const int mblocks = (NN + 127) / 128;          // 391
    const int gwarps  = (NN * 32 + 255) / 256;     // gather grid (blocks of 8 warps)

    // CSR build (recomputed every call — deterministic given inputs)
    zero_deg_k<<<(NN + 255) / 256, 256>>>();
    hist_k<<<(NE + 255) / 256, 256>>>(dst);
    scan_k<<<1, 1024>>>();
    fill_k<<<(NE + 255) / 256, 256>>>(src, dst);

    // ----- layer 1 (K = 768) -----
    sgemm128<<<mblocks, 256>>>(x, 0, W1l, NN, IN_DIM, 0);
    sgemm128<<<mblocks, 256>>>(x, 0, W1r, NN, IN_DIM, 128);
    gather_combine<<<gwarps, 256>>>(b1);
    zero_stats_k<<<1, 256>>>();
    bn_stats_k<<<256, 128>>>();
    bn_norm_k<<<512, 128>>>(g1, be1, 1);

    // ----- layer 2 (K = 128) -----
    sgemm128<<<mblocks, 256>>>(nullptr, 1, W2l, NN, HID, 0);
    sgemm128<<<mblocks, 256>>>(nullptr, 1, W2r, NN, HID, 128);
    gather_combine<<<gwarps, 256>>>(b2);
    zero_stats_k<<<1, 256>>>();
    bn_stats_k<<<256, 128>>>();
    bn_norm_k<<<512, 128>>>(g2, be2, 1);

    // ----- layer 3 (K = 128, no relu) -----
    sgemm128<<<mblocks, 256>>>(nullptr, 1, W3l, NN, HID, 0);
    sgemm128<<<mblocks, 256>>>(nullptr, 1, W3r, NN, HID, 128);
    gather_combine<<<gwarps, 256>>>(b3);
    zero_stats_k<<<1, 256>>>();
    bn_stats_k<<<256, 128>>>();
    bn_norm_k<<<512, 128>>>(g3, be3, 0);

    // ----- pool + head -----
    pool_init_k<<<NG, HID>>>();
    pool_max_k<<<(NN + POOL_CHUNK - 1) / POOL_CHUNK, 128>>>(batch);
    final_linear_k<<<NG, HID>>>(Wlin, blin, out);
}

// round 2
// speedup vs baseline: 1.4797x; 1.4797x over previous
#include <cuda_runtime.h>
#include <cuda_bf16.h>
#include <cstdint>

#define NN      50000
#define NE      400000
#define NG      128
#define IN_DIM  768
#define HID     128
#define NCLS    11
#define BN_EPS  1e-5f

// ---------------- scratch (device globals; no allocation allowed) ----------------
__device__ float    g_y[(size_t)NN * 256];      // [NN,256]: cols 0..127 = h@Wl.T, 128..255 = h@Wr.T
__device__ float    g_hpre[(size_t)NN * HID];   // pre-BN activations
__device__ float    g_h[(size_t)NN * HID];      // post-BN(+relu) activations
__device__ __align__(16) __nv_bfloat16 g_whi[256 * IN_DIM];   // fused [Wl;Wr] hi
__device__ __align__(16) __nv_bfloat16 g_wlo[256 * IN_DIM];   // fused [Wl;Wr] lo
__device__ int      g_deg[NN];
__device__ int      g_off[NN + 1];
__device__ int      g_cursor[NN];
__device__ int      g_csr[NE];                  // src ids bucketed by dst
__device__ float    g_stats[256];               // [0:128)=sum, [128:256)=sumsq
__device__ unsigned g_pool[NG * HID];           // order-preserving-encoded max

// ---------------- helpers ----------------
__device__ __forceinline__ unsigned fenc(float f) {
    unsigned u = __float_as_uint(f);
    return (u >> 31) ? ~u : (u | 0x80000000u);
}
__device__ __forceinline__ float fdec(unsigned e) {
    return (e >> 31) ? __uint_as_float(e & 0x7fffffffu) : __uint_as_float(~e);
}

// ---------------- CSR build ----------------
__global__ void zero_deg_k() {
    int i = blockIdx.x * blockDim.x + threadIdx.x;
    if (i < NN) g_deg[i] = 0;
}

__global__ void hist_k(const int* __restrict__ dst) {
    int e = blockIdx.x * blockDim.x + threadIdx.x;
    if (e < NE) atomicAdd(&g_deg[dst[e]], 1);
}

__global__ void scan_k() {
    __shared__ int sm[1024];
    __shared__ int carry;
    int t = threadIdx.x;
    if (t == 0) carry = 0;
    __syncthreads();
    for (int base = 0; base < NN; base += 1024) {
        int i = base + t;
        int v = (i < NN) ? g_deg[i] : 0;
        sm[t] = v;
        __syncthreads();
        #pragma unroll
        for (int s = 1; s < 1024; s <<= 1) {
            int add = (t >= s) ? sm[t - s] : 0;
            __syncthreads();
            sm[t] += add;
            __syncthreads();
        }
        int excl = carry + sm[t] - v;
        if (i < NN) { g_off[i] = excl; g_cursor[i] = excl; }
        __syncthreads();
        if (t == 0) carry += sm[1023];
        __syncthreads();
    }
    if (t == 0) g_off[NN] = carry;
}

__global__ void fill_k(const int* __restrict__ src, const int* __restrict__ dst) {
    int e = blockIdx.x * blockDim.x + threadIdx.x;
    if (e < NE) {
        int p = atomicAdd(&g_cursor[dst[e]], 1);
        g_csr[p] = src[e];
    }
}

// ---------------- weight conversion: [Wl;Wr] -> bf16 hi/lo ----------------
__global__ void convert_w_k(const float* __restrict__ Wl, const float* __restrict__ Wr, int K) {
    int idx = blockIdx.x * blockDim.x + threadIdx.x;
    if (idx >= 256 * K) return;
    int row = idx / K, col = idx - row * K;
    float v = (row < 128) ? Wl[row * K + col] : Wr[(row - 128) * K + col];
    __nv_bfloat16 hi = __float2bfloat16(v);
    __nv_bfloat16 lo = __float2bfloat16(v - __bfloat162float(hi));
    g_whi[idx] = hi;
    g_wlo[idx] = lo;
}

// ---------------- tensor-core GEMM (bf16 hi/lo split, fp32 accum) ----------------
// Y[M,256] = A[M,K] @ W[256,K]^T, computed as Ahi@Whi + Ahi@Wlo + Alo@Whi.
// BM=128, BN=128 (gridDim.y=2 covers N=256), BK=32. 8 warps, warp tile 32x64.
#define PADK 40

__device__ __forceinline__ void mma16816(float* c, const uint32_t* a, const uint32_t* b) {
    asm volatile(
        "mma.sync.aligned.m16n8k16.row.col.f32.bf16.bf16.f32 "
        "{%0,%1,%2,%3}, {%4,%5,%6,%7}, {%8,%9}, {%0,%1,%2,%3};"
        : "+f"(c[0]), "+f"(c[1]), "+f"(c[2]), "+f"(c[3])
        : "r"(a[0]), "r"(a[1]), "r"(a[2]), "r"(a[3]), "r"(b[0]), "r"(b[1]));
}

__global__ __launch_bounds__(256, 1)
void gemm_tc(const float* __restrict__ Aext, int useH, int M, int K) {
    const float* __restrict__ A = useH ? (const float*)g_h : Aext;
    __shared__ __align__(16) __nv_bfloat16 Ah[128][PADK];
    __shared__ __align__(16) __nv_bfloat16 Al[128][PADK];
    __shared__ __align__(16) __nv_bfloat16 Bh[128][PADK];
    __shared__ __align__(16) __nv_bfloat16 Bl[128][PADK];

    const int tid  = threadIdx.x;
    const int lane = tid & 31;
    const int wid  = tid >> 5;
    const int wm   = wid & 3;        // 4 warps in M
    const int wn   = wid >> 2;       // 2 warps in N
    const int g    = lane >> 2;      // 0..7
    const int tig  = lane & 3;       // 0..3
    const int row0 = blockIdx.x * 128;
    const int n0g  = blockIdx.y * 128;   // global N offset of this block

    float acc[2][8][4];
    #pragma unroll
    for (int i = 0; i < 2; i++)
        #pragma unroll
        for (int j = 0; j < 8; j++)
            #pragma unroll
            for (int q = 0; q < 4; q++) acc[i][j][q] = 0.f;

    for (int k0 = 0; k0 < K; k0 += 32) {
        // ---- A tile: 128 rows x 32 fp32, convert to hi/lo bf16 ----
        #pragma unroll
        for (int i = 0; i < 4; i++) {
            int s  = tid + 256 * i;      // 0..1023
            int r  = s >> 3;
            int c4 = s & 7;              // 4-float segment
            float4 v = make_float4(0.f, 0.f, 0.f, 0.f);
            if (row0 + r < M)
                v = *reinterpret_cast<const float4*>(A + (size_t)(row0 + r) * K + k0 + c4 * 4);
            __nv_bfloat16 h0 = __float2bfloat16(v.x);
            __nv_bfloat16 h1 = __float2bfloat16(v.y);
            __nv_bfloat16 h2 = __float2bfloat16(v.z);
            __nv_bfloat16 h3 = __float2bfloat16(v.w);
            __nv_bfloat16 l0 = __float2bfloat16(v.x - __bfloat162float(h0));
            __nv_bfloat16 l1 = __float2bfloat16(v.y - __bfloat162float(h1));
            __nv_bfloat16 l2 = __float2bfloat16(v.z - __bfloat162float(h2));
            __nv_bfloat16 l3 = __float2bfloat16(v.w - __bfloat162float(h3));
            __nv_bfloat162 hp0 = __halves2bfloat162(h0, h1);
            __nv_bfloat162 hp1 = __halves2bfloat162(h2, h3);
            __nv_bfloat162 lp0 = __halves2bfloat162(l0, l1);
            __nv_bfloat162 lp1 = __halves2bfloat162(l2, l3);
            uint2 hv = make_uint2(*(uint32_t*)&hp0, *(uint32_t*)&hp1);
            uint2 lv = make_uint2(*(uint32_t*)&lp0, *(uint32_t*)&lp1);
            *reinterpret_cast<uint2*>(&Ah[r][c4 * 4]) = hv;
            *reinterpret_cast<uint2*>(&Al[r][c4 * 4]) = lv;
        }
        // ---- B tile: 128 rows x 32 bf16 (hi and lo) ----
        #pragma unroll
        for (int i = 0; i < 2; i++) {
            int s  = tid + 256 * i;      // 0..511
            int r  = s >> 2;
            int c8 = s & 3;              // 8-bf16 segment
            size_t go = (size_t)(n0g + r) * K + k0 + c8 * 8;
            *reinterpret_cast<uint4*>(&Bh[r][c8 * 8]) =
                *reinterpret_cast<const uint4*>(g_whi + go);
            *reinterpret_cast<uint4*>(&Bl[r][c8 * 8]) =
                *reinterpret_cast<const uint4*>(g_wlo + go);
        }
        __syncthreads();

        #pragma unroll
        for (int ks = 0; ks < 2; ks++) {
            const int kk = ks * 16;
            uint32_t ah[2][4], al[2][4];
            #pragma unroll
            for (int mt = 0; mt < 2; mt++) {
                int r = wm * 32 + mt * 16;
                ah[mt][0] = *reinterpret_cast<uint32_t*>(&Ah[r + g][kk + 2 * tig]);
                ah[mt][1] = *reinterpret_cast<uint32_t*>(&Ah[r + g + 8][kk + 2 * tig]);
                ah[mt][2] = *reinterpret_cast<uint32_t*>(&Ah[r + g][kk + 2 * tig + 8]);
                ah[mt][3] = *reinterpret_cast<uint32_t*>(&Ah[r + g + 8][kk + 2 * tig + 8]);
                al[mt][0] = *reinterpret_cast<uint32_t*>(&Al[r + g][kk + 2 * tig]);
                al[mt][1] = *reinterpret_cast<uint32_t*>(&Al[r + g + 8][kk + 2 * tig]);
                al[mt][2] = *reinterpret_cast<uint32_t*>(&Al[r + g][kk + 2 * tig + 8]);
                al[mt][3] = *reinterpret_cast<uint32_t*>(&Al[r + g + 8][kk + 2 * tig + 8]);
            }
            #pragma unroll
            for (int nt = 0; nt < 8; nt++) {
                int c = wn * 64 + nt * 8;
                uint32_t bh[2], bl[2];
                bh[0] = *reinterpret_cast<uint32_t*>(&Bh[c + g][kk + 2 * tig]);
                bh[1] = *reinterpret_cast<uint32_t*>(&Bh[c + g][kk + 2 * tig + 8]);
                bl[0] = *reinterpret_cast<uint32_t*>(&Bl[c + g][kk + 2 * tig]);
                bl[1] = *reinterpret_cast<uint32_t*>(&Bl[c + g][kk + 2 * tig + 8]);
                #pragma unroll
                for (int mt = 0; mt < 2; mt++) {
                    mma16816(acc[mt][nt], ah[mt], bh);   // hi*hi
                    mma16816(acc[mt][nt], ah[mt], bl);   // hi*lo
                    mma16816(acc[mt][nt], al[mt], bh);   // lo*hi
                }
            }
        }
        __syncthreads();
    }

    // ---- store C ----
    #pragma unroll
    for (int mt = 0; mt < 2; mt++) {
        #pragma unroll
        for (int nt = 0; nt < 8; nt++) {
            int r = row0 + wm * 32 + mt * 16 + g;
            int c = n0g + wn * 64 + nt * 8 + 2 * tig;
            if (r < M)
                *reinterpret_cast<float2*>(&g_y[(size_t)r * 256 + c]) =
                    make_float2(acc[mt][nt][0], acc[mt][nt][1]);
            if (r + 8 < M)
                *reinterpret_cast<float2*>(&g_y[(size_t)(r + 8) * 256 + c]) =
                    make_float2(acc[mt][nt][2], acc[mt][nt][3]);
        }
    }
}

// ---------------- gather (CSR) + combine: hpre = mean_agg(yl) + yr + b ----------------
__global__ void gather_combine(const float* __restrict__ bias) {
    int warp = (blockIdx.x * blockDim.x + threadIdx.x) >> 5;
    int lane = threadIdx.x & 31;
    if (warp >= NN) return;
    int e0 = g_off[warp], e1 = g_off[warp + 1];
    float4 acc = make_float4(0.f, 0.f, 0.f, 0.f);
    for (int e = e0; e < e1; e++) {
        int s = g_csr[e];
        float4 v = reinterpret_cast<const float4*>(g_y + (size_t)s * 256)[lane];
        acc.x += v.x; acc.y += v.y; acc.z += v.z; acc.w += v.w;
    }
    float invd = 1.f / fmaxf((float)(e1 - e0), 1.f);
    float4 r  = reinterpret_cast<const float4*>(g_y + (size_t)warp * 256 + 128)[lane];
    float4 b4 = reinterpret_cast<const float4*>(bias)[lane];
    float4 o;
    o.x = acc.x * invd + r.x + b4.x;
    o.y = acc.y * invd + r.y + b4.y;
    o.z = acc.z * invd + r.z + b4.z;
    o.w = acc.w * invd + r.w + b4.w;
    reinterpret_cast<float4*>(g_hpre + (size_t)warp * HID)[lane] = o;
}

// ---------------- BatchNorm ----------------
__global__ void zero_stats_k() { g_stats[threadIdx.x] = 0.f; }

__global__ void bn_stats_k() {
    int f = threadIdx.x;  // 128
    float s = 0.f, s2 = 0.f;
    for (int r = blockIdx.x; r < NN; r += gridDim.x) {
        float v = g_hpre[(size_t)r * HID + f];
        s += v; s2 += v * v;
    }
    atomicAdd(&g_stats[f], s);
    atomicAdd(&g_stats[f + 128], s2);
}

__global__ void bn_norm_k(const float* __restrict__ gamma, const float* __restrict__ beta,
                          int do_relu) {
    int f = threadIdx.x;
    float mean = g_stats[f] * (1.f / NN);
    float var  = g_stats[f + 128] * (1.f / NN) - mean * mean;
    float rstd = rsqrtf(var + BN_EPS);
    float g = gamma[f] * rstd;
    float b = beta[f] - mean * g;
    for (int r = blockIdx.x; r < NN; r += gridDim.x) {
        float v = g_hpre[(size_t)r * HID + f] * g + b;
        if (do_relu) v = fmaxf(v, 0.f);
        g_h[(size_t)r * HID + f] = v;
    }
}

// ---------------- global max pool (batch is sorted) ----------------
__global__ void pool_init_k() {
    g_pool[blockIdx.x * HID + threadIdx.x] = 0x007fffffu;  // fenc(-inf)
}

#define POOL_CHUNK 512
__global__ void pool_max_k(const int* __restrict__ batch) {
    int f = threadIdx.x;  // 128
    int r0 = blockIdx.x * POOL_CHUNK;
    int r1 = min(r0 + POOL_CHUNK, NN);
    int cur = -1;
    float m = -3.4e38f;
    for (int r = r0; r < r1; r++) {
        int gi = batch[r];
        if (gi != cur) {
            if (cur >= 0) atomicMax(&g_pool[cur * HID + f], fenc(m));
            cur = gi;
            m = -3.4e38f;
        }
        m = fmaxf(m, g_h[(size_t)r * HID + f]);
    }
    if (cur >= 0) atomicMax(&g_pool[cur * HID + f], fenc(m));
}

// ---------------- final linear: out[g] = pooled[g] @ Wlin.T + blin ----------------
__global__ void final_linear_k(const float* __restrict__ Wlin, const float* __restrict__ blin,
                               float* __restrict__ out) {
    __shared__ float sh[HID];
    int g = blockIdx.x, t = threadIdx.x;
    sh[t] = fdec(g_pool[g * HID + t]);
    __syncthreads();
    if (t < NCLS) {
        float a = blin[t];
        #pragma unroll 8
        for (int k = 0; k < HID; k++) a += sh[k] * Wlin[t * HID + k];
        out[g * NCLS + t] = a;
    }
}

// ---------------- launch ----------------
extern "C" void kernel_launch(void* const* d_in, const int* in_sizes, int n_in,
                              void* d_out, int out_size) {
    const float* x    = (const float*)d_in[0];
    const int*   src  = (const int*)d_in[1];
    const int*   dst  = src + NE;
    const int*   batch = (const int*)d_in[2];
    const float* W1l = (const float*)d_in[3];
    const float* b1  = (const float*)d_in[4];
    const float* W1r = (const float*)d_in[5];
    const float* g1  = (const float*)d_in[6];
    const float* be1 = (const float*)d_in[7];
    const float* W2l = (const float*)d_in[8];
    const float* b2  = (const float*)d_in[9];
    const float* W2r = (const float*)d_in[10];
    const float* g2  = (const float*)d_in[11];
    const float* be2 = (const float*)d_in[12];
    const float* W3l = (const float*)d_in[13];
    const float* b3  = (const float*)d_in[14];
    const float* W3r = (const float*)d_in[15];
    const float* g3  = (const float*)d_in[16];
    const float* be3 = (const float*)d_in[17];
    const float* Wlin = (const float*)d_in[18];
    const float* blin = (const float*)d_in[19];
    float* out = (float*)d_out;

    const int mblocks = (NN + 127) / 128;          // 391
    const dim3 ggrid(mblocks, 2);
    const int gwarps  = (NN * 32 + 255) / 256;     // gather grid (blocks of 8 warps)

    // CSR build (recomputed every call — deterministic given inputs)
    zero_deg_k<<<(NN + 255) / 256, 256>>>();
    hist_k<<<(NE + 255) / 256, 256>>>(dst);
    scan_k<<<1, 1024>>>();
    fill_k<<<(NE + 255) / 256, 256>>>(src, dst);

    // ----- layer 1 (K = 768) -----
    convert_w_k<<<(256 * IN_DIM + 255) / 256, 256>>>(W1l, W1r, IN_DIM);
    gemm_tc<<<ggrid, 256>>>(x, 0, NN, IN_DIM);
    gather_combine<<<gwarps, 256>>>(b1);
    zero_stats_k<<<1, 256>>>();
    bn_stats_k<<<256, 128>>>();
    bn_norm_k<<<512, 128>>>(g1, be1, 1);

    // ----- layer 2 (K = 128) -----
    convert_w_k<<<(256 * HID + 255) / 256, 256>>>(W2l, W2r, HID);
    gemm_tc<<<ggrid, 256>>>(nullptr, 1, NN, HID);
    gather_combine<<<gwarps, 256>>>(b2);
    zero_stats_k<<<1, 256>>>();
    bn_stats_k<<<256, 128>>>();
    bn_norm_k<<<512, 128>>>(g2, be2, 1);

    // ----- layer 3 (K = 128, no relu) -----
    convert_w_k<<<(256 * HID + 255) / 256, 256>>>(W3l, W3r, HID);
    gemm_tc<<<ggrid, 256>>>(nullptr, 1, NN, HID);
    gather_combine<<<gwarps, 256>>>(b3);
    zero_stats_k<<<1, 256>>>();
    bn_stats_k<<<256, 128>>>();
    bn_norm_k<<<512, 128>>>(g3, be3, 0);

    // ----- pool + head -----
    pool_init_k<<<NG, HID>>>();
    pool_max_k<<<(NN + POOL_CHUNK - 1) / POOL_CHUNK, 128>>>(batch);
    final_linear_k<<<NG, HID>>>(Wlin, blin, out);
}

// round 4
// speedup vs baseline: 1.9761x; 1.3355x over previous
#include <cuda_runtime.h>
#include <cuda_bf16.h>
#include <cstdint>

#define NN      50000
#define NE      400000
#define NG      128
#define IN_DIM  768
#define HID     128
#define NCLS    11
#define BN_EPS  1e-5f

// ---------------- scratch (device globals; no allocation allowed) ----------------
__device__ float    g_y[(size_t)NN * 256];      // [NN,256]: cols 0..127 = h@Wl.T, 128..255 = h@Wr.T
__device__ float    g_hpre[(size_t)NN * HID];   // pre-BN activations
__device__ float    g_h[(size_t)NN * HID];      // post-BN(+relu) activations
__device__ __align__(16) __nv_bfloat16 g_whi[256 * IN_DIM];   // fused [Wl;Wr] hi
__device__ __align__(16) __nv_bfloat16 g_wlo[256 * IN_DIM];   // fused [Wl;Wr] lo
__device__ int      g_deg[NN];
__device__ int      g_start[NN];
__device__ int      g_cursor[NN];
__device__ int      g_total;
__device__ int      g_csr[NE];                  // src ids bucketed by dst (unordered buckets)
__device__ float    g_part[256 * 256];          // bn partials
__device__ unsigned g_pool[NG * HID];           // order-preserving-encoded max

// ---------------- helpers ----------------
__device__ __forceinline__ uint32_t smem_u32(const void* p) {
    uint32_t a;
    asm("{ .reg .u64 t; cvta.to.shared.u64 t, %1; cvt.u32.u64 %0, t; }" : "=r"(a) : "l"(p));
    return a;
}
__device__ __forceinline__ unsigned fenc(float f) {
    unsigned u = __float_as_uint(f);
    return (u >> 31) ? ~u : (u | 0x80000000u);
}
__device__ __forceinline__ float fdec(unsigned e) {
    return (e >> 31) ? __uint_as_float(e & 0x7fffffffu) : __uint_as_float(~e);
}

#define LDMX4(d, a)                                                                  \
    asm volatile("ldmatrix.sync.aligned.m8n8.x4.shared.b16 {%0,%1,%2,%3}, [%4];"     \
        : "=r"((d)[0]), "=r"((d)[1]), "=r"((d)[2]), "=r"((d)[3]) : "r"(a))

#define CPASYNC16(dst, src) \
    asm volatile("cp.async.cg.shared.global [%0], [%1], 16;" :: "r"(dst), "l"(src) : "memory")
#define CPCOMMIT() asm volatile("cp.async.commit_group;" ::: "memory")
#define CPWAIT0()  asm volatile("cp.async.wait_group 0;" ::: "memory")

__device__ __forceinline__ void mma16816(float* c, const uint32_t* a, const uint32_t* b) {
    asm volatile(
        "mma.sync.aligned.m16n8k16.row.col.f32.bf16.bf16.f32 "
        "{%0,%1,%2,%3}, {%4,%5,%6,%7}, {%8,%9}, {%0,%1,%2,%3};"
        : "+f"(c[0]), "+f"(c[1]), "+f"(c[2]), "+f"(c[3])
        : "r"(a[0]), "r"(a[1]), "r"(a[2]), "r"(a[3]), "r"(b[0]), "r"(b[1]));
}

// ---------------- CSR build ----------------
__global__ void zero_deg_k() {
    int i = blockIdx.x * blockDim.x + threadIdx.x;
    if (i < NN) g_deg[i] = 0;
    if (i == 0) g_total = 0;
}

__global__ void hist_k(const int* __restrict__ dst) {
    int e = blockIdx.x * blockDim.x + threadIdx.x;
    if (e < NE) atomicAdd(&g_deg[dst[e]], 1);
}

// warp-aggregated offset allocation (bucket order irrelevant for the gather)
__global__ void alloc_off_k() {
    int i = blockIdx.x * blockDim.x + threadIdx.x;
    int lane = threadIdx.x & 31;
    int d = (i < NN) ? g_deg[i] : 0;
    int inc = d;
    #pragma unroll
    for (int s = 1; s < 32; s <<= 1) {
        int v = __shfl_up_sync(0xffffffffu, inc, s);
        if (lane >= s) inc += v;
    }
    int ex  = inc - d;
    int tot = __shfl_sync(0xffffffffu, inc, 31);
    int base = 0;
    if (lane == 31) base = atomicAdd(&g_total, tot);
    base = __shfl_sync(0xffffffffu, base, 31);
    if (i < NN) { g_start[i] = base + ex; g_cursor[i] = base + ex; }
}

__global__ void fill_k(const int* __restrict__ src, const int* __restrict__ dst) {
    int e = blockIdx.x * blockDim.x + threadIdx.x;
    if (e < NE) {
        int p = atomicAdd(&g_cursor[dst[e]], 1);
        g_csr[p] = src[e];
    }
}

// ---------------- weight conversion: [Wl;Wr] -> bf16 hi/lo ----------------
__global__ void convert_w_k(const float* __restrict__ Wl, const float* __restrict__ Wr, int K) {
    int idx = blockIdx.x * blockDim.x + threadIdx.x;
    if (idx >= 256 * K) return;
    int row = idx / K, col = idx - row * K;
    float v = (row < 128) ? Wl[row * K + col] : Wr[(row - 128) * K + col];
    __nv_bfloat16 hi = __float2bfloat16(v);
    __nv_bfloat16 lo = __float2bfloat16(v - __bfloat162float(hi));
    g_whi[idx] = hi;
    g_wlo[idx] = lo;
}

// ---------------- tensor-core GEMM (bf16 hi/lo, double-buffered, ldmatrix) ----------------
// Y[M,256] = A[M,K] @ W[256,K]^T as Ahi@Whi + Ahi@Wlo + Alo@Whi.
// BM=128, BN=128 (gridDim.y=2), BK=32. 8 warps, warp tile 32x64.
// Padded rows: 40 bf16 (80 B) -> conflict-free ldmatrix and cp.async.
#define PADK  40
#define BUFB  40960                 // Ah(10240) Al(10240) Bh(10240) Bl(10240)
#define GEMM_SMEM (2 * BUFB)

__global__ __launch_bounds__(256)
void gemm_mma(const float* __restrict__ Aext, int useH, int M, int K) {
    const float* __restrict__ A = useH ? (const float*)g_h : Aext;
    extern __shared__ char dsm[];
    const uint32_t sm0 = smem_u32(dsm);

    const int tid  = threadIdx.x;
    const int lane = tid & 31;
    const int wid  = tid >> 5;
    const int wm   = wid & 3;            // 4 warps in M
    const int wn   = wid >> 2;           // 2 warps in N
    const int row0 = blockIdx.x * 128;
    const int n0g  = blockIdx.y * 128;

    // per-lane ldmatrix byte offsets within a tile buffer
    const int a_row = lane & 15;
    const int a_kh  = (lane >> 4) * 8;
    const uint32_t aoff = (uint32_t)(((wm * 32 + a_row) * PADK + a_kh) * 2);
    const int b_row = ((lane >> 4) << 3) + (lane & 7);
    const int b_kh  = ((lane >> 3) & 1) * 8;
    const uint32_t boff = (uint32_t)(((wn * 64 + b_row) * PADK + b_kh) * 2);

    float acc[2][8][4];
    #pragma unroll
    for (int i = 0; i < 2; i++)
        #pragma unroll
        for (int j = 0; j < 8; j++)
            #pragma unroll
            for (int q = 0; q < 4; q++) acc[i][j][q] = 0.f;

    const int ntiles = K / 32;

    auto fill = [&](int t) {
        const int k0 = t * 32;
        const uint32_t base = sm0 + (uint32_t)(t & 1) * BUFB;
        const uint32_t bAh = base, bAl = base + 10240;
        const uint32_t bBh = base + 20480, bBl = base + 30720;
        // A: 128 rows x 32 fp32 -> hi/lo bf16 (1024 float4 segments)
        #pragma unroll
        for (int i = 0; i < 4; i++) {
            int s  = tid + 256 * i;
            int r  = s >> 3;
            int c4 = s & 7;
            float4 v = make_float4(0.f, 0.f, 0.f, 0.f);
            if (row0 + r < M)
                v = *reinterpret_cast<const float4*>(A + (size_t)(row0 + r) * K + k0 + c4 * 4);
            __nv_bfloat16 h0 = __float2bfloat16(v.x), h1 = __float2bfloat16(v.y);
            __nv_bfloat16 h2 = __float2bfloat16(v.z), h3 = __float2bfloat16(v.w);
            __nv_bfloat16 l0 = __float2bfloat16(v.x - __bfloat162float(h0));
            __nv_bfloat16 l1 = __float2bfloat16(v.y - __bfloat162float(h1));
            __nv_bfloat16 l2 = __float2bfloat16(v.z - __bfloat162float(h2));
            __nv_bfloat16 l3 = __float2bfloat16(v.w - __bfloat162float(h3));
            __nv_bfloat162 hp0 = __halves2bfloat162(h0, h1), hp1 = __halves2bfloat162(h2, h3);
            __nv_bfloat162 lp0 = __halves2bfloat162(l0, l1), lp1 = __halves2bfloat162(l2, l3);
            uint32_t off = (uint32_t)((r * PADK + c4 * 4) * 2);
            asm volatile("st.shared.v2.b32 [%0], {%1, %2};" ::
                "r"(bAh + off), "r"(*(uint32_t*)&hp0), "r"(*(uint32_t*)&hp1) : "memory");
            asm volatile("st.shared.v2.b32 [%0], {%1, %2};" ::
                "r"(bAl + off), "r"(*(uint32_t*)&lp0), "r"(*(uint32_t*)&lp1) : "memory");
        }
        // B: 128 rows x 32 bf16 hi+lo via cp.async (512 16B chunks each)
        #pragma unroll
        for (int i = 0; i < 2; i++) {
            int s   = tid + 256 * i;
            int r   = s >> 2;
            int seg = s & 3;
            uint32_t off = (uint32_t)(r * (PADK * 2) + seg * 16);
            const void* sh = (const void*)(g_whi + (size_t)(n0g + r) * K + k0 + seg * 8);
            const void* sl = (const void*)(g_wlo + (size_t)(n0g + r) * K + k0 + seg * 8);
            CPASYNC16(bBh + off, sh);
            CPASYNC16(bBl + off, sl);
        }
        CPCOMMIT();
    };

    fill(0);
    for (int t = 0; t < ntiles; t++) {
        CPWAIT0();
        __syncthreads();
        if (t + 1 < ntiles) fill(t + 1);

        const uint32_t base = sm0 + (uint32_t)(t & 1) * BUFB;
        const uint32_t pAh = base + aoff, pAl = base + 10240 + aoff;
        const uint32_t pBh = base + 20480 + boff, pBl = base + 30720 + boff;
        #pragma unroll
        for (int ks = 0; ks < 2; ks++) {
            const uint32_t ko = (uint32_t)(ks * 32);          // 16 cols * 2B
            uint32_t ah[2][4], al[2][4];
            LDMX4(ah[0], pAh + ko);
            LDMX4(ah[1], pAh + ko + 1280);                    // +16 rows
            LDMX4(al[0], pAl + ko);
            LDMX4(al[1], pAl + ko + 1280);
            #pragma unroll
            for (int p = 0; p < 4; p++) {
                uint32_t bh[4], bl[4];
                LDMX4(bh, pBh + ko + (uint32_t)(p * 1280));   // +16 n-rows per pair
                LDMX4(bl, pBl + ko + (uint32_t)(p * 1280));
                #pragma unroll
                for (int q = 0; q < 2; q++) {
                    const int nt = 2 * p + q;
                    uint32_t bqh[2] = { bh[2 * q], bh[2 * q + 1] };
                    uint32_t bql[2] = { bl[2 * q], bl[2 * q + 1] };
                    mma16816(acc[0][nt], ah[0], bqh);
                    mma16816(acc[0][nt], ah[0], bql);
                    mma16816(acc[0][nt], al[0], bqh);
                    mma16816(acc[1][nt], ah[1], bqh);
                    mma16816(acc[1][nt], ah[1], bql);
                    mma16816(acc[1][nt], al[1], bqh);
                }
            }
        }
    }

    // ---- store C ----
    const int g   = lane >> 2;
    const int tig = lane & 3;
    #pragma unroll
    for (int mt = 0; mt < 2; mt++) {
        #pragma unroll
        for (int nt = 0; nt < 8; nt++) {
            int r = row0 + wm * 32 + mt * 16 + g;
            int c = n0g + wn * 64 + nt * 8 + 2 * tig;
            if (r < M)
                *reinterpret_cast<float2*>(&g_y[(size_t)r * 256 + c]) =
                    make_float2(acc[mt][nt][0], acc[mt][nt][1]);
            if (r + 8 < M)
                *reinterpret_cast<float2*>(&g_y[(size_t)(r + 8) * 256 + c]) =
                    make_float2(acc[mt][nt][2], acc[mt][nt][3]);
        }
    }
}

// ---------------- gather (bucketed) + combine ----------------
__global__ void gather_combine(const float* __restrict__ bias) {
    int warp = (blockIdx.x * blockDim.x + threadIdx.x) >> 5;
    int lane = threadIdx.x & 31;
    if (warp >= NN) return;
    int e0 = g_start[warp];
    int deg = g_deg[warp];
    int e1 = e0 + deg;
    float4 a0 = make_float4(0.f, 0.f, 0.f, 0.f);
    float4 a1 = make_float4(0.f, 0.f, 0.f, 0.f);
    float4 a2 = make_float4(0.f, 0.f, 0.f, 0.f);
    float4 a3 = make_float4(0.f, 0.f, 0.f, 0.f);
    int e = e0;
    for (; e + 4 <= e1; e += 4) {
        int s0 = g_csr[e], s1 = g_csr[e + 1], s2 = g_csr[e + 2], s3 = g_csr[e + 3];
        float4 v0 = reinterpret_cast<const float4*>(g_y + (size_t)s0 * 256)[lane];
        float4 v1 = reinterpret_cast<const float4*>(g_y + (size_t)s1 * 256)[lane];
        float4 v2 = reinterpret_cast<const float4*>(g_y + (size_t)s2 * 256)[lane];
        float4 v3 = reinterpret_cast<const float4*>(g_y + (size_t)s3 * 256)[lane];
        a0.x += v0.x; a0.y += v0.y; a0.z += v0.z; a0.w += v0.w;
        a1.x += v1.x; a1.y += v1.y; a1.z += v1.z; a1.w += v1.w;
        a2.x += v2.x; a2.y += v2.y; a2.z += v2.z; a2.w += v2.w;
        a3.x += v3.x; a3.y += v3.y; a3.z += v3.z; a3.w += v3.w;
    }
    for (; e < e1; e++) {
        int s = g_csr[e];
        float4 v = reinterpret_cast<const float4*>(g_y + (size_t)s * 256)[lane];
        a0.x += v.x; a0.y += v.y; a0.z += v.z; a0.w += v.w;
    }
    float4 acc;
    acc.x = (a0.x + a1.x) + (a2.x + a3.x);
    acc.y = (a0.y + a1.y) + (a2.y + a3.y);
    acc.z = (a0.z + a1.z) + (a2.z + a3.z);
    acc.w = (a0.w + a1.w) + (a2.w + a3.w);
    float invd = 1.f / fmaxf((float)deg, 1.f);
    float4 r  = reinterpret_cast<const float4*>(g_y + (size_t)warp * 256 + 128)[lane];
    float4 b4 = reinterpret_cast<const float4*>(bias)[lane];
    float4 o;
    o.x = acc.x * invd + r.x + b4.x;
    o.y = acc.y * invd + r.y + b4.y;
    o.z = acc.z * invd + r.z + b4.z;
    o.w = acc.w * invd + r.w + b4.w;
    reinterpret_cast<float4*>(g_hpre + (size_t)warp * HID)[lane] = o;
}

// ---------------- BatchNorm ----------------
__global__ void bn_stats_k() {       // 256 blocks, no atomics / no zeroing
    int f = threadIdx.x;             // 128
    float s = 0.f, s2 = 0.f;
    for (int r = blockIdx.x; r < NN; r += 256) {
        float v = g_hpre[(size_t)r * HID + f];
        s += v; s2 += v * v;
    }
    g_part[blockIdx.x * 256 + f]       = s;
    g_part[blockIdx.x * 256 + 128 + f] = s2;
}

__global__ void bn_norm_k(const float* __restrict__ gamma, const float* __restrict__ beta,
                          int do_relu) {
    int f = threadIdx.x;
    float s = 0.f, s2 = 0.f;
    #pragma unroll 4
    for (int b = 0; b < 256; b++) {
        s  += g_part[b * 256 + f];
        s2 += g_part[b * 256 + 128 + f];
    }
    float mean = s * (1.f / NN);
    float var  = s2 * (1.f / NN) - mean * mean;
    float rstd = rsqrtf(var + BN_EPS);
    float g = gamma[f] * rstd;
    float b = beta[f] - mean * g;
    for (int r = blockIdx.x; r < NN; r += gridDim.x) {
        float v = g_hpre[(size_t)r * HID + f] * g + b;
        if (do_relu) v = fmaxf(v, 0.f);
        g_h[(size_t)r * HID + f] = v;
    }
}

// ---------------- global max pool (batch is sorted) ----------------
__global__ void pool_init_k() {
    g_pool[blockIdx.x * HID + threadIdx.x] = 0x007fffffu;  // fenc(-inf)
}

#define POOL_CHUNK 512
__global__ void pool_max_k(const int* __restrict__ batch) {
    int f = threadIdx.x;  // 128
    int r0 = blockIdx.x * POOL_CHUNK;
    int r1 = min(r0 + POOL_CHUNK, NN);
    int cur = -1;
    float m = -3.4e38f;
    for (int r = r0; r < r1; r++) {
        int gi = batch[r];
        if (gi != cur) {
            if (cur >= 0) atomicMax(&g_pool[cur * HID + f], fenc(m));
            cur = gi;
            m = -3.4e38f;
        }
        m = fmaxf(m, g_h[(size_t)r * HID + f]);
    }
    if (cur >= 0) atomicMax(&g_pool[cur * HID + f], fenc(m));
}

// ---------------- final linear ----------------
__global__ void final_linear_k(const float* __restrict__ Wlin, const float* __restrict__ blin,
                               float* __restrict__ out) {
    __shared__ float sh[HID];
    int g = blockIdx.x, t = threadIdx.x;
    sh[t] = fdec(g_pool[g * HID + t]);
    __syncthreads();
    if (t < NCLS) {
        float a = blin[t];
        #pragma unroll 8
        for (int k = 0; k < HID; k++) a += sh[k] * Wlin[t * HID + k];
        out[g * NCLS + t] = a;
    }
}

// ---------------- launch ----------------
extern "C" void kernel_launch(void* const* d_in, const int* in_sizes, int n_in,
                              void* d_out, int out_size) {
    const float* x    = (const float*)d_in[0];
    const int*   src  = (const int*)d_in[1];
    const int*   dst  = src + NE;
    const int*   batch = (const int*)d_in[2];
    const float* W1l = (const float*)d_in[3];
    const float* b1  = (const float*)d_in[4];
    const float* W1r = (const float*)d_in[5];
    const float* g1  = (const float*)d_in[6];
    const float* be1 = (const float*)d_in[7];
    const float* W2l = (const float*)d_in[8];
    const float* b2  = (const float*)d_in[9];
    const float* W2r = (const float*)d_in[10];
    const float* g2  = (const float*)d_in[11];
    const float* be2 = (const float*)d_in[12];
    const float* W3l = (const float*)d_in[13];
    const float* b3  = (const float*)d_in[14];
    const float* W3r = (const float*)d_in[15];
    const float* g3  = (const float*)d_in[16];
    const float* be3 = (const float*)d_in[17];
    const float* Wlin = (const float*)d_in[18];
    const float* blin = (const float*)d_in[19];
    float* out = (float*)d_out;

    cudaFuncSetAttribute(gemm_mma, cudaFuncAttributeMaxDynamicSharedMemorySize, GEMM_SMEM);

    const int mblocks = (NN + 127) / 128;          // 391
    const dim3 ggrid(mblocks, 2);
    const int gwarps  = (NN * 32 + 255) / 256;

    // CSR build
    zero_deg_k<<<(NN + 255) / 256, 256>>>();
    hist_k<<<(NE + 255) / 256, 256>>>(dst);
    alloc_off_k<<<(NN + 255) / 256, 256>>>();
    fill_k<<<(NE + 255) / 256, 256>>>(src, dst);

    // ----- layer 1 (K = 768) -----
    convert_w_k<<<(256 * IN_DIM + 255) / 256, 256>>>(W1l, W1r, IN_DIM);
    gemm_mma<<<ggrid, 256, GEMM_SMEM>>>(x, 0, NN, IN_DIM);
    gather_combine<<<gwarps, 256>>>(b1);
    bn_stats_k<<<256, 128>>>();
    bn_norm_k<<<512, 128>>>(g1, be1, 1);

    // ----- layer 2 (K = 128) -----
    convert_w_k<<<(256 * HID + 255) / 256, 256>>>(W2l, W2r, HID);
    gemm_mma<<<ggrid, 256, GEMM_SMEM>>>(nullptr, 1, NN, HID);
    gather_combine<<<gwarps, 256>>>(b2);
    bn_stats_k<<<256, 128>>>();
    bn_norm_k<<<512, 128>>>(g2, be2, 1);

    // ----- layer 3 (K = 128, no relu) -----
    convert_w_k<<<(256 * HID + 255) / 256, 256>>>(W3l, W3r, HID);
    gemm_mma<<<ggrid, 256, GEMM_SMEM>>>(nullptr, 1, NN, HID);
    gather_combine<<<gwarps, 256>>>(b3);
    bn_stats_k<<<256, 128>>>();
    bn_norm_k<<<512, 128>>>(g3, be3, 0);

    // ----- pool + head -----
    pool_init_k<<<NG, HID>>>();
    pool_max_k<<<(NN + POOL_CHUNK - 1) / POOL_CHUNK, 128>>>(batch);
    final_linear_k<<<NG, HID>>>(Wlin, blin, out);
}